// round 15
// baseline (speedup 1.0000x reference)
#include <cuda_runtime.h>
#include <cuda_bf16.h>

#define H 1024
#define V 32000
#define L 64
#define E 3
#define EOS_TOK 1
#define NT 512                     // threads per block in k_all
#define NWPB 16                    // warps per block in k_all
#define NDTASK (V + 3 * H + L)     // phase-D tasks: proj + gh2 + awh2

// ---------------- device scratch (no allocations allowed) ----------------
__device__ __align__(16) float g_X[E * L * H];        // gathered encoder inputs
__device__ __align__(16) float g_giA[E * L * 3 * H];  // W_ih @ x partial (K first half)
__device__ __align__(16) float g_giB[E * L * 3 * H];  // W_ih @ x partial (K second half)
__device__ float g_outs[E * L * H];                   // per-encoder outputs (= hidden chain)
__device__ __align__(16) float g_zero[H];             // stays zero (module init)
__device__ float g_encouts[L * H];                    // combined encoder outputs
__device__ __align__(16) float g_M[L * H];            // TRANSPOSED: g_M[l*H+j] = Wc_a[j].enc_l
__device__ __align__(16) float g_hbuf[2][H];          // decoder hidden double buffer
__device__ __align__(16) float g_ghbuf[2][3 * H];     // dW_hh @ h, parity-matched to hbuf
__device__ float g_awhbuf[2][L];                      // W_attn_h @ h, parity-matched
__device__ float g_We[H];                             // Wc_e @ e (per step)
__device__ float g_awe[L];                            // attn logit e-partial
__device__ float g_raw[V];                            // raw output logits (bf16-weight path)
__device__ float g_blocksum2[256];                    // per-block sum of exp
__device__ float g_blockcmax[256];                    // per-block max raw
__device__ float g_blockabs[256];                     // per-block max sum|w||h|
__device__ __align__(16) __nv_bfloat16 g_Wbf[(size_t)V * H];  // bf16 copy of W_out
__device__ volatile unsigned g_flags[256];            // full-barrier arrival flags
__device__ volatile unsigned g_rel;                   // full-barrier release
__device__ volatile unsigned g_gflags[3][96];         // encoder group barrier flags
__device__ volatile unsigned g_grel[3];               // encoder group release

// ---------------- helpers ----------------
__device__ __forceinline__ float sigmoidf_(float x) { return 1.0f / (1.0f + expf(-x)); }

__device__ __forceinline__ float wred(float s) {
    #pragma unroll
    for (int o = 16; o; o >>= 1) s += __shfl_down_sync(0xffffffffu, s, o);
    return s;
}

// 16-lane segmented reduce; m must be the caller's half-warp mask so the two
// halves of a warp may be at different control-flow points (divergent trip counts)
__device__ __forceinline__ float red16m(float s, unsigned m) {
    #pragma unroll
    for (int o = 8; o; o >>= 1) s += __shfl_down_sync(m, s, o, 16);
    return s;
}

// per-lane partial of dot over H=1024 with 32 lanes; caller must wred
__device__ __forceinline__ float dotH_lane(const float* __restrict__ row,
                                           const float* __restrict__ vec, int lane) {
    const float4* r4 = (const float4*)row;
    const float4* v4 = (const float4*)vec;
    float s = 0.f;
    #pragma unroll
    for (int i = 0; i < 8; i++) {
        float4 a = r4[i * 32 + lane], b = v4[i * 32 + lane];
        s += a.x * b.x + a.y * b.y + a.z * b.z + a.w * b.w;
    }
    return s;
}

// per-lane partial of dot over H=1024 with 16 lanes; caller must red16m
__device__ __forceinline__ float dotH_16(const float* __restrict__ row,
                                         const float* __restrict__ vec, int l16) {
    const float4* r4 = (const float4*)row;
    const float4* v4 = (const float4*)vec;
    float s = 0.f;
    #pragma unroll
    for (int i = 0; i < 16; i++) {
        float4 a = r4[i * 16 + l16], b = v4[i * 16 + l16];
        s += a.x * b.x + a.y * b.y + a.z * b.z + a.w * b.w;
    }
    return s;
}

__device__ __forceinline__ unsigned f2mono(float x) {
    unsigned u = __float_as_uint(x);
    return (u & 0x80000000u) ? ~u : (u | 0x80000000u);
}

// full grid barrier: per-block flag stores + block-0 scan + release flag
__device__ __forceinline__ void gsyncf(int nblk, unsigned& gen) {
    unsigned g = gen + 1u;
    __syncthreads();
    if (threadIdx.x == 0) {
        __threadfence();                       // release: publish prior writes
        g_flags[blockIdx.x] = g;
    }
    if (blockIdx.x == 0) {
        if (threadIdx.x < nblk) { while (g_flags[threadIdx.x] < g) {} }
        __syncthreads();
        if (threadIdx.x == 0) { __threadfence(); g_rel = g; }
    } else {
        if (threadIdx.x == 0) { while (g_rel < g) {} __threadfence(); }
    }
    __syncthreads();
    gen = g;
}

// group barrier among blocks [gbase, gbase+gcnt)
__device__ __forceinline__ void gsyncg(int grp, int gbase, int gcnt, unsigned& gen) {
    unsigned g = gen + 1u;
    __syncthreads();
    if (threadIdx.x == 0) {
        __threadfence();
        g_gflags[grp][blockIdx.x - gbase] = g;
    }
    if (blockIdx.x == gbase) {
        if (threadIdx.x < gcnt) { while (g_gflags[grp][threadIdx.x] < g) {} }
        __syncthreads();
        if (threadIdx.x == 0) { __threadfence(); g_grel[grp] = g; }
    } else {
        if (threadIdx.x == 0) { while (g_grel[grp] < g) {} __threadfence(); }
    }
    __syncthreads();
    gen = g;
}

// ---------------- init ----------------
__global__ void k_init() {
    int i = threadIdx.x;
    if (i < H) g_hbuf[0][i] = 0.0f;
    for (int j = i; j < 3 * H; j += 1024) g_ghbuf[0][j] = 0.0f;
    if (i < L) g_awhbuf[0][i] = 0.0f;
    if (i < 256) g_flags[i] = 0u;
    if (i < 288) g_gflags[i / 96][i % 96] = 0u;
    if (i == 0) { g_rel = 0u; g_grel[0] = 0u; g_grel[1] = 0u; g_grel[2] = 0u; }
}

// ---------------- convert W_out to bf16 (once per launch) ----------------
__global__ void k_prep(const float* __restrict__ W) {
    size_t i8 = ((size_t)blockIdx.x * 256 + threadIdx.x) * 8;
    const float4* W4 = (const float4*)W;
    float4 a = W4[i8 >> 2], b = W4[(i8 >> 2) + 1];
    __nv_bfloat16 tmp[8];
    tmp[0] = __float2bfloat16_rn(a.x); tmp[1] = __float2bfloat16_rn(a.y);
    tmp[2] = __float2bfloat16_rn(a.z); tmp[3] = __float2bfloat16_rn(a.w);
    tmp[4] = __float2bfloat16_rn(b.x); tmp[5] = __float2bfloat16_rn(b.y);
    tmp[6] = __float2bfloat16_rn(b.z); tmp[7] = __float2bfloat16_rn(b.w);
    *(uint4*)(g_Wbf + i8) = *(uint4*)tmp;
}

// ---------------- encoder: gather embeddings ----------------
__global__ void k_gather(const int* __restrict__ qids, const int* __restrict__ cids,
                         const float* __restrict__ emb) {
    int e = blockIdx.x / L, t = blockIdx.x % L;
    int id = (e == 0) ? qids[t] : cids[(e - 1) * L + t];
    const float* src = emb + ((long long)e * V + id) * H;
    float* dst = g_X + (e * L + t) * H;
    for (int j = threadIdx.x; j < H; j += blockDim.x) dst[j] = src[j];
}

// ---- gi partials = W_ih @ X (64x64 tile, 4x4 reg blocking, split-K 2-way) ----
__global__ __launch_bounds__(256) void k_gi2(const float* __restrict__ W) {
    __shared__ __align__(16) float Ws[64][68];
    __shared__ __align__(16) float Xs[64][68];
    int kh = blockIdx.x / 144;                       // K half: 0 or 1
    int rem = blockIdx.x % 144;
    int e = rem / 48, rt = rem % 48;
    int row0 = rt * 64;
    const float* Wb = W + ((long long)e * 3072 + row0) * H;
    const float* Xb = g_X + e * L * H;
    float* gout = kh ? g_giB : g_giA;
    int tx = threadIdx.x & 15, ty = threadIdx.x >> 4;
    float acc[4][4] = {};
    for (int kt = kh * 8; kt < kh * 8 + 8; kt++) {
        for (int i = threadIdx.x; i < 1024; i += 256) {
            int r = i >> 4, c4 = i & 15;
            *(float4*)&Ws[r][c4 * 4] = *(const float4*)(Wb + (long long)r * H + kt * 64 + c4 * 4);
            *(float4*)&Xs[r][c4 * 4] = *(const float4*)(Xb + r * H + kt * 64 + c4 * 4);
        }
        __syncthreads();
        #pragma unroll
        for (int k4 = 0; k4 < 16; k4++) {
            float4 wv[4], xv[4];
            #pragma unroll
            for (int i = 0; i < 4; i++) wv[i] = *(const float4*)&Ws[ty * 4 + i][k4 * 4];
            #pragma unroll
            for (int i = 0; i < 4; i++) xv[i] = *(const float4*)&Xs[tx * 4 + i][k4 * 4];
            #pragma unroll
            for (int i = 0; i < 4; i++)
                #pragma unroll
                for (int j = 0; j < 4; j++)
                    acc[i][j] += wv[i].x * xv[j].x + wv[i].y * xv[j].y
                               + wv[i].z * xv[j].z + wv[i].w * xv[j].w;
        }
        __syncthreads();
    }
    #pragma unroll
    for (int i = 0; i < 4; i++) {
        int row = row0 + ty * 4 + i;
        #pragma unroll
        for (int j = 0; j < 4; j++) {
            int tokn = tx * 4 + j;
            gout[(e * L + tokn) * 3072 + row] = acc[i][j];
        }
    }
}

// ---------------- persistent kernel: encoder recurrence + full decode -----
__global__ __launch_bounds__(NT, 1) void k_all(
    const float* __restrict__ enc_Whh, const float* __restrict__ enc_bih,
    const float* __restrict__ enc_bhh,
    const float* __restrict__ dec_emb, const float* __restrict__ W_attn,
    const float* __restrict__ b_attn, const float* __restrict__ W_comb,
    const float* __restrict__ b_comb, const float* __restrict__ dW_ih,
    const float* __restrict__ dW_hh, const float* __restrict__ db_ih,
    const float* __restrict__ db_hh, const float* __restrict__ W_out,
    const float* __restrict__ b_out, float* __restrict__ logits_out,
    float* __restrict__ attns_out, float* __restrict__ toks_out, int nblk) {

    __shared__ __align__(16) float sbuf[H];          // staging (M phase)
    __shared__ __align__(16) float s_xv[H];          // xvec (BC phase)
    __shared__ float s_raw[L], s_aw[L];
    __shared__ float s_r1[NT], s_r2[NT], s_r3[NT];
    __shared__ int s_cand[64];
    __shared__ unsigned long long s_cpk[64];
    __shared__ int s_cnt;

    const int tid = threadIdx.x, lane = tid & 31, wid = tid >> 5;
    const int gw = blockIdx.x * NWPB + wid;
    const int nwarp = nblk * NWPB;
    const int l16 = lane & 15;
    const unsigned hm = (lane < 16) ? 0x0000FFFFu : 0xFFFF0000u;
    unsigned gen = 0, ggen = 0;
    int tok = 0, done = 0, cur = 0;    // replicated decode state (deterministic)

    // ---- encoder group assignment ----
    const int b1 = nblk / 3, b2 = (2 * nblk) / 3;
    const int grp = (blockIdx.x < b1) ? 0 : ((blockIdx.x < b2) ? 1 : 2);
    const int gbase = (grp == 0) ? 0 : ((grp == 1) ? b1 : b2);
    const int gcnt = (grp == 0) ? b1 : ((grp == 1) ? (b2 - b1) : (nblk - b2));

    // ================= encoder recurrence: 3 independent groups =============
    {
        const int nhw = gcnt * 32;                   // half-warps in group
        const int lhw = ((blockIdx.x - gbase) * NWPB + wid) * 2 + (lane >> 4);
        const int r0 = (int)(((long long)lhw * H) / nhw);
        const int r1 = (int)(((long long)(lhw + 1) * H) / nhw);
        const int e = grp;
        const float* W = enc_Whh + (long long)e * 3 * H * H;
        for (int t = 0; t < L; t++) {
            const float* hin = (t == 0) ? g_zero : (g_outs + (e * L + t - 1) * H);
            for (int hi = r0; hi < r1; hi++) {
                const float4* h4 = (const float4*)hin;
                const float4* w0 = (const float4*)(W + (long long)hi * H);
                const float4* w1 = (const float4*)(W + (long long)(H + hi) * H);
                const float4* w2 = (const float4*)(W + (long long)(2 * H + hi) * H);
                float a0 = 0.f, a1 = 0.f, a2 = 0.f;
                #pragma unroll
                for (int i = 0; i < 16; i++) {
                    int j = i * 16 + l16;
                    float4 hv = h4[j];
                    float4 v0 = w0[j], v1 = w1[j], v2 = w2[j];
                    a0 += v0.x * hv.x + v0.y * hv.y + v0.z * hv.z + v0.w * hv.w;
                    a1 += v1.x * hv.x + v1.y * hv.y + v1.z * hv.z + v1.w * hv.w;
                    a2 += v2.x * hv.x + v2.y * hv.y + v2.z * hv.z + v2.w * hv.w;
                }
                // half-warp masks: trip counts may differ between warp halves
                a0 = red16m(a0, hm); a1 = red16m(a1, hm); a2 = red16m(a2, hm);
                if (l16 == 0) {
                    const float* giA = g_giA + (e * L + t) * 3 * H;
                    const float* giB = g_giB + (e * L + t) * 3 * H;
                    const float* bi = enc_bih + e * 3 * H;
                    const float* bh = enc_bhh + e * 3 * H;
                    float rr = sigmoidf_(giA[hi] + giB[hi] + bi[hi] + a0 + bh[hi]);
                    float z = sigmoidf_(giA[H + hi] + giB[H + hi] + bi[H + hi] + a1 + bh[H + hi]);
                    float n = tanhf(giA[2 * H + hi] + giB[2 * H + hi] + bi[2 * H + hi]
                                    + rr * (a2 + bh[2 * H + hi]));
                    g_outs[(e * L + t) * H + hi] = (1.0f - z) * n + z * hin[hi];
                }
            }
            gsyncg(grp, gbase, gcnt, ggen);
        }
    }
    gsyncf(nblk, gen);

    // ================= combine encoder outputs =================
    for (int i = blockIdx.x * NT + tid; i < L * H; i += nblk * NT)
        g_encouts[i] = g_outs[i] + 0.5f * (g_outs[L * H + i] + g_outs[2 * L * H + i]);
    gsyncf(nblk, gen);

    // ================= M^T: g_M[l*H + j] = Wc_a[j] . enc_l (one-time) ========
    if (blockIdx.x < 64) {
        int j = blockIdx.x * NWPB + wid;                 // 0..1023
        float4 wreg[8];
        const float4* Wr = (const float4*)(W_comb + (long long)j * 2 * H + H);
        #pragma unroll
        for (int i = 0; i < 8; i++) wreg[i] = Wr[i * 32 + lane];
        for (int l = 0; l < L; l++) {
            for (int i = tid; i < 256; i += NT)
                ((float4*)sbuf)[i] = ((const float4*)(g_encouts + l * H))[i];
            __syncthreads();
            float s = 0.f;
            #pragma unroll
            for (int i = 0; i < 8; i++) {
                float4 ev = ((const float4*)sbuf)[i * 32 + lane];
                s += wreg[i].x * ev.x + wreg[i].y * ev.y + wreg[i].z * ev.z + wreg[i].w * ev.w;
            }
            s = wred(s);
            if (lane == 0) g_M[l * H + j] = s;
            __syncthreads();
        }
    }
    gsyncf(nblk, gen);

    // ================= greedy attention decode (3 barriers/step) =============
    for (int t = 0; t < L; t++) {
        // ---- phase A: reduce stats of step t-1, exact argmax, token update,
        //      logits row t-1, then embedding-side dots (We, awe) ----
        if (t > 0) {
            float s = 0.f, am = 0.f, cm = -3.0e38f;
            if (tid < nblk) { s = g_blocksum2[tid]; am = g_blockabs[tid]; cm = g_blockcmax[tid]; }
            s_r1[tid] = s; s_r2[tid] = cm; s_r3[tid] = am;
            if (tid == 0) s_cnt = 0;
            __syncthreads();
            for (int o = NT / 2; o; o >>= 1) {
                if (tid < o) {
                    s_r1[tid] += s_r1[tid + o];
                    s_r2[tid] = fmaxf(s_r2[tid], s_r2[tid + o]);
                    s_r3[tid] = fmaxf(s_r3[tid], s_r3[tid + o]);
                }
                __syncthreads();
            }
            float logZ = logf(s_r1[0]);
            float tau = s_r3[0] * (1.5f / 512.0f) + 1e-6f;
            float thr = s_r2[0] - 2.0f * tau;
            for (int i = tid; i < V; i += NT) {
                if (g_raw[i] >= thr) {
                    int p = atomicAdd(&s_cnt, 1);
                    if (p < 64) s_cand[p] = i;
                }
            }
            __syncthreads();
            int nc = min(s_cnt, 64);
            const float* h2p = g_hbuf[cur ^ 1];          // h2 of step t-1
            for (int c = wid; c < nc; c += NWPB) {
                int v = s_cand[c];
                float d = dotH_lane(W_out + (size_t)v * H, h2p, lane);
                d = wred(d);
                if (lane == 0)
                    s_cpk[c] = (((unsigned long long)f2mono(d + b_out[v])) << 32)
                             | (unsigned)(0xFFFFFFFFu - (unsigned)v);
            }
            __syncthreads();
            unsigned long long best = 0ull;
            for (int c = 0; c < nc; c++) if (s_cpk[c] > best) best = s_cpk[c];
            int nxt = (int)(0xFFFFFFFFu - (unsigned)(best & 0xFFFFFFFFull));
            int tokout = done ? tok : nxt;
            if (blockIdx.x == 0 && tid == 0) toks_out[t - 1] = (float)tokout;
            tok = tokout;
            if (!done) cur ^= 1;                         // accept h2 + speculated gh/awh
            done = done | (nxt == EOS_TOK);
            for (int i = blockIdx.x * NT + tid; i < V; i += nblk * NT)
                logits_out[(long long)(t - 1) * V + i] = g_raw[i] - logZ;
        }
        {
            const float* evec = dec_emb + (long long)tok * H;
            const int nhwG = nwarp * 2;
            const int ghw = gw * 2 + (lane >> 4);
            int q0 = (int)(((long long)ghw * (H + L)) / nhwG);
            int q1 = (int)(((long long)(ghw + 1) * (H + L)) / nhwG);
            for (int q = q0; q < q1; q++) {
                if (q < H) {
                    float s = dotH_16(W_comb + (long long)q * 2 * H, evec, l16);
                    s = red16m(s, hm);
                    if (l16 == 0) g_We[q] = s;
                } else {
                    int l = q - H;
                    float s = dotH_16(W_attn + l * 2 * H, evec, l16);
                    s = red16m(s, hm);
                    if (l16 == 0) g_awe[l] = s;
                }
            }
        }
        gsyncf(nblk, gen);

        // ---- phase BC (blocks 0..63): softmax + xvec (SMEM) + GRU -> h2 ----
        if (blockIdx.x < 64) {
            if (tid < L) s_raw[tid] = g_awe[tid] + g_awhbuf[cur][tid] + b_attn[tid];
            __syncthreads();
            if (tid < L) {
                float m = -3.0e38f;
                for (int l = 0; l < L; l++) m = fmaxf(m, s_raw[l]);
                float ss = 0.f;
                for (int l = 0; l < L; l++) ss += expf(s_raw[l] - m);
                s_aw[tid] = expf(s_raw[tid] - m) / ss;
            }
            __syncthreads();
            if (blockIdx.x == 0 && tid < L) attns_out[t * L + tid] = s_aw[tid];
            // xvec: thread covers 2 adjacent j via float2 reads of M^T rows
            {
                int j0 = wid * 64 + lane * 2;
                float ax = 0.f, ay = 0.f;
                #pragma unroll 8
                for (int l = 0; l < L; l++) {
                    float2 m2 = *(const float2*)&g_M[l * H + j0];
                    float a = s_aw[l];
                    ax += m2.x * a; ay += m2.y * a;
                }
                s_xv[j0] = fmaxf(ax + g_We[j0] + b_comb[j0], 0.0f);
                s_xv[j0 + 1] = fmaxf(ay + g_We[j0 + 1] + b_comb[j0 + 1], 0.0f);
            }
            __syncthreads();
            // GRU gates: warp per hidden unit hi
            {
                int hi = blockIdx.x * NWPB + wid;        // 0..1023
                const float4* xv4 = (const float4*)s_xv;
                const float4* i0 = (const float4*)(dW_ih + (long long)hi * H);
                const float4* i1 = (const float4*)(dW_ih + (long long)(H + hi) * H);
                const float4* i2 = (const float4*)(dW_ih + (long long)(2 * H + hi) * H);
                float gi0 = 0.f, gi1 = 0.f, gi2 = 0.f;
                #pragma unroll
                for (int i = 0; i < 8; i++) {
                    int j = i * 32 + lane;
                    float4 xv = xv4[j];
                    float4 wa = i0[j], wb = i1[j], wc = i2[j];
                    gi0 += wa.x * xv.x + wa.y * xv.y + wa.z * xv.z + wa.w * xv.w;
                    gi1 += wb.x * xv.x + wb.y * xv.y + wb.z * xv.z + wb.w * xv.w;
                    gi2 += wc.x * xv.x + wc.y * xv.y + wc.z * xv.z + wc.w * xv.w;
                }
                gi0 = wred(gi0); gi1 = wred(gi1); gi2 = wred(gi2);
                if (lane == 0) {
                    const float* gh = g_ghbuf[cur];
                    float hv = g_hbuf[cur][hi];
                    float rr = sigmoidf_(gi0 + db_ih[hi] + gh[hi] + db_hh[hi]);
                    float z = sigmoidf_(gi1 + db_ih[H + hi] + gh[H + hi] + db_hh[H + hi]);
                    float n = tanhf(gi2 + db_ih[2 * H + hi]
                                    + rr * (gh[2 * H + hi] + db_hh[2 * H + hi]));
                    g_hbuf[cur ^ 1][hi] = (1.0f - z) * n + z * hv;
                }
            }
        }
        gsyncf(nblk, gen);

        // ---- phase D: bf16 projection + stats + SPECULATIVE gh2/awh2 -------
        {
            const int curN = cur ^ 1;
            const float* h2 = g_hbuf[curN];
            float4 hr[8];
            const float4* h4 = (const float4*)h2;
            #pragma unroll
            for (int jj = 0; jj < 4; jj++) {
                hr[2 * jj] = h4[(jj * 32 + lane) * 2];
                hr[2 * jj + 1] = h4[(jj * 32 + lane) * 2 + 1];
            }
            float se = 0.f, rm = -3.0e38f, ab = 0.f;
            for (int q = gw; q < NDTASK; q += nwarp) {
                if (q < V) {
                    const uint4* Wr = (const uint4*)(g_Wbf + (size_t)q * H);
                    float acc = 0.f, aa = 0.f;
                    #pragma unroll
                    for (int jj = 0; jj < 4; jj++) {
                        uint4 u = Wr[jj * 32 + lane];
                        float4 ha = hr[2 * jj], hb = hr[2 * jj + 1];
                        float2 p0 = __bfloat1622float2(*(const __nv_bfloat162*)&u.x);
                        float2 p1 = __bfloat1622float2(*(const __nv_bfloat162*)&u.y);
                        float2 p2 = __bfloat1622float2(*(const __nv_bfloat162*)&u.z);
                        float2 p3 = __bfloat1622float2(*(const __nv_bfloat162*)&u.w);
                        acc += p0.x * ha.x + p0.y * ha.y + p1.x * ha.z + p1.y * ha.w
                             + p2.x * hb.x + p2.y * hb.y + p3.x * hb.z + p3.y * hb.w;
                        aa += fabsf(p0.x * ha.x) + fabsf(p0.y * ha.y) + fabsf(p1.x * ha.z)
                            + fabsf(p1.y * ha.w) + fabsf(p2.x * hb.x) + fabsf(p2.y * hb.y)
                            + fabsf(p3.x * hb.z) + fabsf(p3.y * hb.w);
                    }
                    acc = wred(acc); aa = wred(aa);
                    if (lane == 0) {
                        float raw = acc + b_out[q];
                        g_raw[q] = raw;
                        se += expf(raw);
                        rm = fmaxf(rm, raw);
                        ab = fmaxf(ab, aa);
                    }
                } else if (q < V + 3 * H) {
                    int r = q - V;
                    float d = wred(dotH_lane(dW_hh + (long long)r * H, h2, lane));
                    if (lane == 0) g_ghbuf[curN][r] = d;
                } else {
                    int l = q - V - 3 * H;
                    float d = wred(dotH_lane(W_attn + l * 2 * H + H, h2, lane));
                    if (lane == 0) g_awhbuf[curN][l] = d;
                }
            }
            if (lane == 0) { s_r1[wid] = se; s_r2[wid] = rm; s_r3[wid] = ab; }
            __syncthreads();
            if (tid == 0) {
                float s = 0.f, m = -3.0e38f, a = 0.f;
                #pragma unroll
                for (int i = 0; i < NWPB; i++) {
                    s += s_r1[i]; m = fmaxf(m, s_r2[i]); a = fmaxf(a, s_r3[i]);
                }
                g_blocksum2[blockIdx.x] = s;
                g_blockcmax[blockIdx.x] = m;
                g_blockabs[blockIdx.x] = a;
            }
        }
        gsyncf(nblk, gen);
    }

    // ================= epilogue: step L-1 token + final logits row ==========
    {
        float s = 0.f, am = 0.f, cm = -3.0e38f;
        if (tid < nblk) { s = g_blocksum2[tid]; am = g_blockabs[tid]; cm = g_blockcmax[tid]; }
        s_r1[tid] = s; s_r2[tid] = cm; s_r3[tid] = am;
        if (tid == 0) s_cnt = 0;
        __syncthreads();
        for (int o = NT / 2; o; o >>= 1) {
            if (tid < o) {
                s_r1[tid] += s_r1[tid + o];
                s_r2[tid] = fmaxf(s_r2[tid], s_r2[tid + o]);
                s_r3[tid] = fmaxf(s_r3[tid], s_r3[tid + o]);
            }
            __syncthreads();
        }
        float logZ = logf(s_r1[0]);
        if (blockIdx.x == 0) {
            float tau = s_r3[0] * (1.5f / 512.0f) + 1e-6f;
            float thr = s_r2[0] - 2.0f * tau;
            for (int i = tid; i < V; i += NT) {
                if (g_raw[i] >= thr) {
                    int p = atomicAdd(&s_cnt, 1);
                    if (p < 64) s_cand[p] = i;
                }
            }
            __syncthreads();
            int nc = min(s_cnt, 64);
            const float* h2p = g_hbuf[cur ^ 1];
            for (int c = wid; c < nc; c += NWPB) {
                int v = s_cand[c];
                float d = dotH_lane(W_out + (size_t)v * H, h2p, lane);
                d = wred(d);
                if (lane == 0)
                    s_cpk[c] = (((unsigned long long)f2mono(d + b_out[v])) << 32)
                             | (unsigned)(0xFFFFFFFFu - (unsigned)v);
            }
            __syncthreads();
            if (tid == 0) {
                unsigned long long best = 0ull;
                for (int c = 0; c < nc; c++) if (s_cpk[c] > best) best = s_cpk[c];
                int nxt = (int)(0xFFFFFFFFu - (unsigned)(best & 0xFFFFFFFFull));
                toks_out[L - 1] = (float)(done ? tok : nxt);
            }
        }
        for (int i = blockIdx.x * NT + tid; i < V; i += nblk * NT)
            logits_out[(long long)(L - 1) * V + i] = g_raw[i] - logZ;
    }
}

// ---------------- host launch ----------------
extern "C" void kernel_launch(void* const* d_in, const int* in_sizes, int n_in,
                              void* d_out, int out_size) {
    const int* qids      = (const int*)d_in[0];
    const int* cids      = (const int*)d_in[1];
    const float* enc_emb = (const float*)d_in[2];
    const float* enc_Wih = (const float*)d_in[3];
    const float* enc_Whh = (const float*)d_in[4];
    const float* enc_bih = (const float*)d_in[5];
    const float* enc_bhh = (const float*)d_in[6];
    const float* dec_emb = (const float*)d_in[7];
    const float* W_attn  = (const float*)d_in[8];
    const float* b_attn  = (const float*)d_in[9];
    const float* W_comb  = (const float*)d_in[10];
    const float* b_comb  = (const float*)d_in[11];
    const float* dW_ih   = (const float*)d_in[12];
    const float* dW_hh   = (const float*)d_in[13];
    const float* db_ih   = (const float*)d_in[14];
    const float* db_hh   = (const float*)d_in[15];
    const float* W_out   = (const float*)d_in[16];
    const float* b_out   = (const float*)d_in[17];

    float* out        = (float*)d_out;
    float* logits_out = out;
    float* attns_out  = out + (long long)L * V;
    float* toks_out   = attns_out + L * L;

    int dev = 0, sms = 148;
    cudaGetDevice(&dev);
    cudaDeviceGetAttribute(&sms, cudaDevAttrMultiProcessorCount, dev);
    int nblk = sms;
    if (nblk > 256) nblk = 256;
    if (nblk < 96) nblk = 96;   // BC/M phases need >= 64 working blocks

    k_init<<<1, 1024>>>();
    k_prep<<<(V * H) / (8 * 256), 256>>>(W_out);
    k_gather<<<E * L, 256>>>(qids, cids, enc_emb);
    k_gi2<<<E * 48 * 2, 256>>>(enc_Wih);
    k_all<<<nblk, NT>>>(enc_Whh, enc_bih, enc_bhh, dec_emb, W_attn, b_attn,
                        W_comb, b_comb, dW_ih, dW_hh, db_ih, db_hh, W_out, b_out,
                        logits_out, attns_out, toks_out, nblk);
}